// round 16
// baseline (speedup 1.0000x reference)
#include <cuda_runtime.h>
#include <cuda_bf16.h>
#include <cstdint>
#include <math.h>

#define BB      128
#define DD      (512*512)          // 262144
#define KT      64                 // k elements per stage
#define NTILES  (DD/KT)            // 4096
#define NCTA    148
#define THREADS 512

// ---- scratch (__device__ globals; zero-initialized at module load,
//      re-zeroed by the in-kernel finalize for graph replays) ----
__device__ float g_dots[BB*BB];    // REDG-accumulated dots
__device__ float g_xn2[BB];        // REDG-accumulated norms
__device__ float g_yn2[BB];
__device__ int   g_tick;

__device__ __forceinline__ uint32_t smem_u32(const void* p) {
    uint32_t a;
    asm("{ .reg .u64 t; cvta.to.shared.u64 t, %1; cvt.u32.u64 %0, t; }" : "=r"(a) : "l"(p));
    return a;
}
#define SW128(o) ((uint32_t)(o) ^ ((((uint32_t)(o)) >> 3) & 0x70))

// fp32 pair -> packed bf16x2 hi + bf16x2 lo (memory order [a,b], a in low half)
__device__ __forceinline__ void cvt_hilo(float a, float b, uint32_t& h, uint32_t& l) {
    asm("cvt.rn.bf16x2.f32 %0, %1, %2;" : "=r"(h) : "f"(b), "f"(a));
    float fa = __uint_as_float(h << 16);
    float fb = __uint_as_float(h & 0xffff0000u);
    float la = a - fa, lb = b - fb;
    asm("cvt.rn.bf16x2.f32 %0, %1, %2;" : "=r"(l) : "f"(lb), "f"(la));
}

#define LDSM4(r, addr)                                                          \
    asm volatile("ldmatrix.sync.aligned.m8n8.x4.shared.b16 {%0,%1,%2,%3}, [%4];"\
        : "=r"((r)[0]), "=r"((r)[1]), "=r"((r)[2]), "=r"((r)[3]) : "r"(addr))

#define MMA16816(d, a0, a1, a2, a3, b0, b1)                                     \
    asm volatile("mma.sync.aligned.m16n8k16.row.col.f32.bf16.bf16.f32 "         \
        "{%0,%1,%2,%3}, {%4,%5,%6,%7}, {%8,%9}, {%0,%1,%2,%3};"                 \
        : "+f"((d)[0]), "+f"((d)[1]), "+f"((d)[2]), "+f"((d)[3])                \
        : "r"(a0), "r"(a1), "r"(a2), "r"(a3), "r"(b0), "r"(b1))

// SMEM: 2 stages x 4 tiles (Xh,Xl,Yh,Yl), each 128 rows x 128B (SW128) = 16KB
#define TILE_OFF(p, w) ((p)*65536 + (w)*16384)
#define SMEM_TOTAL (2*65536)

__global__ void __launch_bounds__(THREADS, 1)
gemm_tc_kernel(const float* __restrict__ X, const float* __restrict__ Y,
               float* __restrict__ out) {
    extern __shared__ char smem[];
    __shared__ int s_last;
    const uint32_t sbase = smem_u32(smem);
    const int t    = threadIdx.x;
    const int lane = t & 31;
    const int w    = t >> 5;          // warps 0-7: producers; 8-15: consumers
    const int c    = blockIdx.x;

    const int t0 = (int)(((long long)c       * NTILES) / NCTA);
    const int t1 = (int)(((long long)(c + 1) * NTILES) / NCTA);
    const int NT = t1 - t0;

    if (w >= 8) {
        // ---------------- CONSUMER: 32x64 output tile per warp (champion loop) ----------------
        const int cw = w - 8;
        const int rb = (cw >> 1) * 32;     // row band
        const int cb = (cw & 1) * 64;      // col half

        const int a_row = rb + (lane & 7) + ((lane >> 3) & 1) * 8;
        const int a_kb  = ((lane >> 4) & 1) * 16;
        const int b_row = cb + (lane & 7) + ((lane >> 3) & 1) * 8;
        const int b_kb  = ((lane >> 4) & 1) * 16;

        float acc[16][4];
        #pragma unroll
        for (int j = 0; j < 16; j++)
            #pragma unroll
            for (int q = 0; q < 4; q++) acc[j][q] = 0.0f;

        __syncthreads();   // stage 0 ready

        for (int s = 0; s < NT; s++) {
            const int p = s & 1;
            const uint32_t xh = sbase + TILE_OFF(p, 0);
            const uint32_t xl = sbase + TILE_OFF(p, 1);
            const uint32_t yh = sbase + TILE_OFF(p, 2);
            const uint32_t yl = sbase + TILE_OFF(p, 3);
            #pragma unroll
            for (int kk = 0; kk < 4; kk++) {
                uint32_t ah[8], al[8];
                const uint32_t aoff0 = SW128(a_row * 128 + kk * 32 + a_kb);
                const uint32_t aoff1 = SW128((a_row + 16) * 128 + kk * 32 + a_kb);
                LDSM4(ah + 0, xh + aoff0);
                LDSM4(ah + 4, xh + aoff1);
                LDSM4(al + 0, xl + aoff0);
                LDSM4(al + 4, xl + aoff1);
                #pragma unroll
                for (int nh = 0; nh < 2; nh++) {
                    uint32_t bh[8], bl[8];
                    const uint32_t boff0 = SW128((b_row + nh * 32) * 128 + kk * 32 + b_kb);
                    const uint32_t boff1 = SW128((b_row + nh * 32 + 16) * 128 + kk * 32 + b_kb);
                    LDSM4(bh + 0, yh + boff0);
                    LDSM4(bh + 4, yh + boff1);
                    LDSM4(bl + 0, yl + boff0);
                    LDSM4(bl + 4, yl + boff1);
                    // term order: hh, hl, lh (champion ordering)
                    #pragma unroll
                    for (int m = 0; m < 2; m++) {
                        MMA16816(acc[m*8+nh*4+0], ah[m*4+0],ah[m*4+1],ah[m*4+2],ah[m*4+3], bh[0], bh[2]);
                        MMA16816(acc[m*8+nh*4+1], ah[m*4+0],ah[m*4+1],ah[m*4+2],ah[m*4+3], bh[1], bh[3]);
                        MMA16816(acc[m*8+nh*4+2], ah[m*4+0],ah[m*4+1],ah[m*4+2],ah[m*4+3], bh[4], bh[6]);
                        MMA16816(acc[m*8+nh*4+3], ah[m*4+0],ah[m*4+1],ah[m*4+2],ah[m*4+3], bh[5], bh[7]);
                    }
                    #pragma unroll
                    for (int m = 0; m < 2; m++) {
                        MMA16816(acc[m*8+nh*4+0], ah[m*4+0],ah[m*4+1],ah[m*4+2],ah[m*4+3], bl[0], bl[2]);
                        MMA16816(acc[m*8+nh*4+1], ah[m*4+0],ah[m*4+1],ah[m*4+2],ah[m*4+3], bl[1], bl[3]);
                        MMA16816(acc[m*8+nh*4+2], ah[m*4+0],ah[m*4+1],ah[m*4+2],ah[m*4+3], bl[4], bl[6]);
                        MMA16816(acc[m*8+nh*4+3], ah[m*4+0],ah[m*4+1],ah[m*4+2],ah[m*4+3], bl[5], bl[7]);
                    }
                    #pragma unroll
                    for (int m = 0; m < 2; m++) {
                        MMA16816(acc[m*8+nh*4+0], al[m*4+0],al[m*4+1],al[m*4+2],al[m*4+3], bh[0], bh[2]);
                        MMA16816(acc[m*8+nh*4+1], al[m*4+0],al[m*4+1],al[m*4+2],al[m*4+3], bh[1], bh[3]);
                        MMA16816(acc[m*8+nh*4+2], al[m*4+0],al[m*4+1],al[m*4+2],al[m*4+3], bh[4], bh[6]);
                        MMA16816(acc[m*8+nh*4+3], al[m*4+0],al[m*4+1],al[m*4+2],al[m*4+3], bh[5], bh[7]);
                    }
                }
            }
            __syncthreads();
        }

        // epilogue: REDG-accumulate partial dots into g_dots
        {
            const int r0 = rb + (lane >> 2);
            const int c0 = cb + (lane & 3) * 2;
            #pragma unroll
            for (int m = 0; m < 2; m++)
                #pragma unroll
                for (int nh = 0; nh < 2; nh++)
                    #pragma unroll
                    for (int jj = 0; jj < 4; jj++) {
                        const int j = m * 8 + nh * 4 + jj;
                        const int col = c0 + nh * 32 + jj * 8;
                        atomicAdd(&g_dots[(r0 + m*16) * BB + col],     acc[j][0]);
                        atomicAdd(&g_dots[(r0 + m*16) * BB + col + 1], acc[j][1]);
                        atomicAdd(&g_dots[(r0 + m*16 + 8) * BB + col],     acc[j][2]);
                        atomicAdd(&g_dots[(r0 + m*16 + 8) * BB + col + 1], acc[j][3]);
                    }
        }
    } else {
        // ---------------- PRODUCER: LDG two stages ahead, store one ahead ----------------
        const int tp   = w * 32 + lane;         // 0..255
        const int prow = tp >> 4;               // rows prow + 16*i, i<8
        const int pf4  = tp & 15;

        float snx[8], sny[8];
        #pragma unroll
        for (int i = 0; i < 8; i++) { snx[i] = 0.f; sny[i] = 0.f; }

        float4 vx[2][4], vy[2][4];

        auto load_half = [&](int kt, int h) {
            const long long kb = (long long)kt * KT + pf4 * 4;
            #pragma unroll
            for (int i = 0; i < 4; i++) {
                const int row = prow + 16 * (4 * h + i);
                vx[h][i] = __ldg((const float4*)(X + (long long)row * DD + kb));
                vy[h][i] = __ldg((const float4*)(Y + (long long)row * DD + kb));
            }
        };
        auto store_half = [&](int p, int h) {
            char* xh = smem + TILE_OFF(p, 0);
            char* xl = smem + TILE_OFF(p, 1);
            char* yh = smem + TILE_OFF(p, 2);
            char* yl = smem + TILE_OFF(p, 3);
            #pragma unroll
            for (int i = 0; i < 4; i++) {
                const int ii = 4 * h + i;
                const int row = prow + 16 * ii;
                const uint32_t off = SW128(row * 128 + pf4 * 8);
                const float4 v = vx[h][i];
                snx[ii] += v.x*v.x + v.y*v.y + v.z*v.z + v.w*v.w;
                uint32_t h0, l0, h1, l1;
                cvt_hilo(v.x, v.y, h0, l0);
                cvt_hilo(v.z, v.w, h1, l1);
                *(uint2*)(xh + off) = make_uint2(h0, h1);
                *(uint2*)(xl + off) = make_uint2(l0, l1);
                const float4 u = vy[h][i];
                sny[ii] += u.x*u.x + u.y*u.y + u.z*u.z + u.w*u.w;
                cvt_hilo(u.x, u.y, h0, l0);
                cvt_hilo(u.z, u.w, h1, l1);
                *(uint2*)(yh + off) = make_uint2(h0, h1);
                *(uint2*)(yl + off) = make_uint2(l0, l1);
            }
        };

        load_half(t0, 0); load_half(t0, 1);
        store_half(0, 0); store_half(0, 1);
        if (NT > 1) { load_half(t0 + 1, 0); load_half(t0 + 1, 1); }
        __syncthreads();   // stage 0 ready

        for (int s = 0; s < NT; s++) {
            if (s + 1 < NT) {
                const int p = (s + 1) & 1;
                store_half(p, 0);
                if (s + 2 < NT) load_half(t0 + s + 2, 0);
                store_half(p, 1);
                if (s + 2 < NT) load_half(t0 + s + 2, 1);
            }
            __syncthreads();
        }

        // norm partials -> REDG accumulate
        #pragma unroll
        for (int i = 0; i < 8; i++) {
            float a = snx[i], b = sny[i];
            #pragma unroll
            for (int o = 8; o >= 1; o >>= 1) {
                a += __shfl_xor_sync(0xffffffffu, a, o);
                b += __shfl_xor_sync(0xffffffffu, b, o);
            }
            if (pf4 == 0) {
                const int row = prow + 16 * i;
                atomicAdd(&g_xn2[row], a);
                atomicAdd(&g_yn2[row], b);
            }
        }
    }

    // ---------------- grid ticket: last CTA runs the finalize in-place ----------------
    __threadfence();       // order this CTA's atomics before the tick
    __syncthreads();
    if (t == 0) s_last = (atomicAdd(&g_tick, 1) == NCTA - 1) ? 1 : 0;
    __syncthreads();
    if (!s_last) return;
    __threadfence();       // acquire: all other CTAs' atomics now visible

    // smem scratch for finalize (stage buffers are dead)
    float* s_xn  = (float*)smem;             // [128]
    float* s_yn  = s_xn + BB;                // [128]
    float* s_vd  = s_yn + BB;                // [128]
    int*   s_cnt = (int*)(s_vd + BB);        // [128]
    int*   s_t1  = s_cnt + BB;
    int*   s_t10 = s_t1 + 1;

    if (t < BB) {
        s_xn[t] = sqrtf(g_xn2[t]);
        s_yn[t] = sqrtf(g_yn2[t]);
        s_cnt[t] = 0;
    }
    if (t == 0) { *s_t1 = 0; *s_t10 = 0; }
    __syncthreads();
    if (t < BB) {
        s_vd[t] = g_dots[t * BB + t] / fmaxf(s_xn[t] * s_yn[t], 1e-8f);
    }
    __syncthreads();

    // sim column j: v_i = dots[i][j]/max(xn_i*yn_j, eps); rank = #gt + #(eq & i<j)
    {
        const int j = t & 127;
        const int h = t >> 7;              // i-quarter
        const float ynj = s_yn[j];
        const float vd  = s_vd[j];
        int cnt = 0;
        #pragma unroll 8
        for (int q = 0; q < 32; q++) {
            const int i = h * 32 + q;
            const float v = g_dots[i * BB + j] / fmaxf(s_xn[i] * ynj, 1e-8f);
            if (i != j) {
                if (v > vd) cnt++;
                else if (v == vd && i < j) cnt++;
            }
        }
        if (cnt) atomicAdd(&s_cnt[j], cnt);
    }
    __syncthreads();

    if (t < BB) {
        const int rank = s_cnt[t];
        const unsigned m1  = __ballot_sync(0xffffffffu, rank == 0);
        const unsigned m10 = __ballot_sync(0xffffffffu, rank < 10);
        if ((t & 31) == 0) {
            atomicAdd(s_t1,  __popc(m1));
            atomicAdd(s_t10, __popc(m10));
        }
    }
    __syncthreads();

    if (t == 0) {
        out[0] = (float)*s_t1  / (float)BB;
        out[1] = (float)*s_t10 / (float)BB;
    }

    // restore zero state for the next graph replay
    for (int q = t; q < BB * BB; q += THREADS) g_dots[q] = 0.f;
    if (t < BB) { g_xn2[t] = 0.f; g_yn2[t] = 0.f; }
    if (t == 0) g_tick = 0;
}

extern "C" void kernel_launch(void* const* d_in, const int* in_sizes, int n_in,
                              void* d_out, int out_size) {
    const float* Z = (const float*)d_in[0];
    const float* Y = (const float*)d_in[1];
    float* out = (float*)d_out;

    cudaFuncSetAttribute(gemm_tc_kernel, cudaFuncAttributeMaxDynamicSharedMemorySize, SMEM_TOTAL);
    gemm_tc_kernel<<<NCTA, THREADS, SMEM_TOTAL>>>(Z, Y, out);
}

// round 17
// speedup vs baseline: 1.1170x; 1.1170x over previous
#include <cuda_runtime.h>
#include <cuda_bf16.h>
#include <cstdint>
#include <math.h>

#define BB      128
#define DD      (512*512)          // 262144
#define KT      64                 // k elements per stage
#define NTILES  (DD/KT)            // 4096
#define NCTA    148
#define THREADS 512

// ---- scratch (__device__ globals; zero-initialized at module load,
//      re-zeroed by finalize's last CTA for graph replays) ----
__device__ float g_dots[BB*BB];    // REDG-accumulated dots
__device__ float g_xn2[BB];        // REDG-accumulated norms
__device__ float g_yn2[BB];
__device__ int   g_it1, g_it10, g_tick;

__device__ __forceinline__ uint32_t smem_u32(const void* p) {
    uint32_t a;
    asm("{ .reg .u64 t; cvta.to.shared.u64 t, %1; cvt.u32.u64 %0, t; }" : "=r"(a) : "l"(p));
    return a;
}
#define SW128(o) ((uint32_t)(o) ^ ((((uint32_t)(o)) >> 3) & 0x70))

// fp32 pair -> packed bf16x2 hi + bf16x2 lo (memory order [a,b], a in low half)
__device__ __forceinline__ void cvt_hilo(float a, float b, uint32_t& h, uint32_t& l) {
    asm("cvt.rn.bf16x2.f32 %0, %1, %2;" : "=r"(h) : "f"(b), "f"(a));
    float fa = __uint_as_float(h << 16);
    float fb = __uint_as_float(h & 0xffff0000u);
    float la = a - fa, lb = b - fb;
    asm("cvt.rn.bf16x2.f32 %0, %1, %2;" : "=r"(l) : "f"(lb), "f"(la));
}

#define LDSM4(r, addr)                                                          \
    asm volatile("ldmatrix.sync.aligned.m8n8.x4.shared.b16 {%0,%1,%2,%3}, [%4];"\
        : "=r"((r)[0]), "=r"((r)[1]), "=r"((r)[2]), "=r"((r)[3]) : "r"(addr))

#define MMA16816(d, a0, a1, a2, a3, b0, b1)                                     \
    asm volatile("mma.sync.aligned.m16n8k16.row.col.f32.bf16.bf16.f32 "         \
        "{%0,%1,%2,%3}, {%4,%5,%6,%7}, {%8,%9}, {%0,%1,%2,%3};"                 \
        : "+f"((d)[0]), "+f"((d)[1]), "+f"((d)[2]), "+f"((d)[3])                \
        : "r"(a0), "r"(a1), "r"(a2), "r"(a3), "r"(b0), "r"(b1))

// SMEM: 2 stages x 4 tiles (Xh,Xl,Yh,Yl), each 128 rows x 128B (SW128) = 16KB
#define TILE_OFF(p, w) ((p)*65536 + (w)*16384)
#define SMEM_TOTAL (2*65536)

__global__ void __launch_bounds__(THREADS, 1)
gemm_tc_kernel(const float* __restrict__ X, const float* __restrict__ Y) {
    extern __shared__ char smem[];
    const uint32_t sbase = smem_u32(smem);
    const int t    = threadIdx.x;
    const int lane = t & 31;
    const int w    = t >> 5;          // warps 0-7: producers; 8-15: consumers
    const int c    = blockIdx.x;

    const int t0 = (int)(((long long)c       * NTILES) / NCTA);
    const int t1 = (int)(((long long)(c + 1) * NTILES) / NCTA);
    const int NT = t1 - t0;

    if (w >= 8) {
        // ---------------- CONSUMER: 32x64 output tile per warp (champion loop) ----------------
        const int cw = w - 8;
        const int rb = (cw >> 1) * 32;     // row band
        const int cb = (cw & 1) * 64;      // col half

        const int a_row = rb + (lane & 7) + ((lane >> 3) & 1) * 8;
        const int a_kb  = ((lane >> 4) & 1) * 16;
        const int b_row = cb + (lane & 7) + ((lane >> 3) & 1) * 8;
        const int b_kb  = ((lane >> 4) & 1) * 16;

        float acc[16][4];
        #pragma unroll
        for (int j = 0; j < 16; j++)
            #pragma unroll
            for (int q = 0; q < 4; q++) acc[j][q] = 0.0f;

        __syncthreads();   // stage 0 ready

        for (int s = 0; s < NT; s++) {
            const int p = s & 1;
            const uint32_t xh = sbase + TILE_OFF(p, 0);
            const uint32_t xl = sbase + TILE_OFF(p, 1);
            const uint32_t yh = sbase + TILE_OFF(p, 2);
            const uint32_t yl = sbase + TILE_OFF(p, 3);
            #pragma unroll
            for (int kk = 0; kk < 4; kk++) {
                uint32_t ah[8], al[8];
                const uint32_t aoff0 = SW128(a_row * 128 + kk * 32 + a_kb);
                const uint32_t aoff1 = SW128((a_row + 16) * 128 + kk * 32 + a_kb);
                LDSM4(ah + 0, xh + aoff0);
                LDSM4(ah + 4, xh + aoff1);
                LDSM4(al + 0, xl + aoff0);
                LDSM4(al + 4, xl + aoff1);
                #pragma unroll
                for (int nh = 0; nh < 2; nh++) {
                    uint32_t bh[8], bl[8];
                    const uint32_t boff0 = SW128((b_row + nh * 32) * 128 + kk * 32 + b_kb);
                    const uint32_t boff1 = SW128((b_row + nh * 32 + 16) * 128 + kk * 32 + b_kb);
                    LDSM4(bh + 0, yh + boff0);
                    LDSM4(bh + 4, yh + boff1);
                    LDSM4(bl + 0, yl + boff0);
                    LDSM4(bl + 4, yl + boff1);
                    // term order: hh, hl, lh (champion ordering)
                    #pragma unroll
                    for (int m = 0; m < 2; m++) {
                        MMA16816(acc[m*8+nh*4+0], ah[m*4+0],ah[m*4+1],ah[m*4+2],ah[m*4+3], bh[0], bh[2]);
                        MMA16816(acc[m*8+nh*4+1], ah[m*4+0],ah[m*4+1],ah[m*4+2],ah[m*4+3], bh[1], bh[3]);
                        MMA16816(acc[m*8+nh*4+2], ah[m*4+0],ah[m*4+1],ah[m*4+2],ah[m*4+3], bh[4], bh[6]);
                        MMA16816(acc[m*8+nh*4+3], ah[m*4+0],ah[m*4+1],ah[m*4+2],ah[m*4+3], bh[5], bh[7]);
                    }
                    #pragma unroll
                    for (int m = 0; m < 2; m++) {
                        MMA16816(acc[m*8+nh*4+0], ah[m*4+0],ah[m*4+1],ah[m*4+2],ah[m*4+3], bl[0], bl[2]);
                        MMA16816(acc[m*8+nh*4+1], ah[m*4+0],ah[m*4+1],ah[m*4+2],ah[m*4+3], bl[1], bl[3]);
                        MMA16816(acc[m*8+nh*4+2], ah[m*4+0],ah[m*4+1],ah[m*4+2],ah[m*4+3], bl[4], bl[6]);
                        MMA16816(acc[m*8+nh*4+3], ah[m*4+0],ah[m*4+1],ah[m*4+2],ah[m*4+3], bl[5], bl[7]);
                    }
                    #pragma unroll
                    for (int m = 0; m < 2; m++) {
                        MMA16816(acc[m*8+nh*4+0], al[m*4+0],al[m*4+1],al[m*4+2],al[m*4+3], bh[0], bh[2]);
                        MMA16816(acc[m*8+nh*4+1], al[m*4+0],al[m*4+1],al[m*4+2],al[m*4+3], bh[1], bh[3]);
                        MMA16816(acc[m*8+nh*4+2], al[m*4+0],al[m*4+1],al[m*4+2],al[m*4+3], bh[4], bh[6]);
                        MMA16816(acc[m*8+nh*4+3], al[m*4+0],al[m*4+1],al[m*4+2],al[m*4+3], bh[5], bh[7]);
                    }
                }
            }
            __syncthreads();
        }

        // epilogue: REDG-accumulate partial dots into g_dots
        {
            const int r0 = rb + (lane >> 2);
            const int c0 = cb + (lane & 3) * 2;
            #pragma unroll
            for (int m = 0; m < 2; m++)
                #pragma unroll
                for (int nh = 0; nh < 2; nh++)
                    #pragma unroll
                    for (int jj = 0; jj < 4; jj++) {
                        const int j = m * 8 + nh * 4 + jj;
                        const int col = c0 + nh * 32 + jj * 8;
                        atomicAdd(&g_dots[(r0 + m*16) * BB + col],     acc[j][0]);
                        atomicAdd(&g_dots[(r0 + m*16) * BB + col + 1], acc[j][1]);
                        atomicAdd(&g_dots[(r0 + m*16 + 8) * BB + col],     acc[j][2]);
                        atomicAdd(&g_dots[(r0 + m*16 + 8) * BB + col + 1], acc[j][3]);
                    }
        }
    } else {
        // ---------------- PRODUCER: LDG two stages ahead, store one ahead ----------------
        const int tp   = w * 32 + lane;         // 0..255
        const int prow = tp >> 4;               // rows prow + 16*i, i<8
        const int pf4  = tp & 15;

        float snx[8], sny[8];
        #pragma unroll
        for (int i = 0; i < 8; i++) { snx[i] = 0.f; sny[i] = 0.f; }

        float4 vx[2][4], vy[2][4];

        auto load_half = [&](int kt, int h) {
            const long long kb = (long long)kt * KT + pf4 * 4;
            #pragma unroll
            for (int i = 0; i < 4; i++) {
                const int row = prow + 16 * (4 * h + i);
                vx[h][i] = __ldg((const float4*)(X + (long long)row * DD + kb));
                vy[h][i] = __ldg((const float4*)(Y + (long long)row * DD + kb));
            }
        };
        auto store_half = [&](int p, int h) {
            char* xh = smem + TILE_OFF(p, 0);
            char* xl = smem + TILE_OFF(p, 1);
            char* yh = smem + TILE_OFF(p, 2);
            char* yl = smem + TILE_OFF(p, 3);
            #pragma unroll
            for (int i = 0; i < 4; i++) {
                const int ii = 4 * h + i;
                const int row = prow + 16 * ii;
                const uint32_t off = SW128(row * 128 + pf4 * 8);
                const float4 v = vx[h][i];
                snx[ii] += v.x*v.x + v.y*v.y + v.z*v.z + v.w*v.w;
                uint32_t h0, l0, h1, l1;
                cvt_hilo(v.x, v.y, h0, l0);
                cvt_hilo(v.z, v.w, h1, l1);
                *(uint2*)(xh + off) = make_uint2(h0, h1);
                *(uint2*)(xl + off) = make_uint2(l0, l1);
                const float4 u = vy[h][i];
                sny[ii] += u.x*u.x + u.y*u.y + u.z*u.z + u.w*u.w;
                cvt_hilo(u.x, u.y, h0, l0);
                cvt_hilo(u.z, u.w, h1, l1);
                *(uint2*)(yh + off) = make_uint2(h0, h1);
                *(uint2*)(yl + off) = make_uint2(l0, l1);
            }
        };

        load_half(t0, 0); load_half(t0, 1);
        store_half(0, 0); store_half(0, 1);
        if (NT > 1) { load_half(t0 + 1, 0); load_half(t0 + 1, 1); }
        __syncthreads();   // stage 0 ready

        for (int s = 0; s < NT; s++) {
            if (s + 1 < NT) {
                const int p = (s + 1) & 1;
                store_half(p, 0);
                if (s + 2 < NT) load_half(t0 + s + 2, 0);
                store_half(p, 1);
                if (s + 2 < NT) load_half(t0 + s + 2, 1);
            }
            __syncthreads();
        }

        // norm partials -> REDG accumulate into 128-entry arrays
        #pragma unroll
        for (int i = 0; i < 8; i++) {
            float a = snx[i], b = sny[i];
            #pragma unroll
            for (int o = 8; o >= 1; o >>= 1) {
                a += __shfl_xor_sync(0xffffffffu, a, o);
                b += __shfl_xor_sync(0xffffffffu, b, o);
            }
            if (pf4 == 0) {
                const int row = prow + 16 * i;
                atomicAdd(&g_xn2[row], a);
                atomicAdd(&g_yn2[row], b);
            }
        }
    }
}

// minimal finalize: CTA j handles sim column j. All inputs pre-reduced:
// one g_dots load + two norm loads per thread. JAX ties: lower index wins.
// Last CTA (ticket) writes output and restores zero-state for graph replay.
__global__ void __launch_bounds__(BB, 1) finalize_kernel(float* __restrict__ out) {
    __shared__ float s_xn[BB];
    __shared__ float s_vd;
    __shared__ int s_gt, s_eqb, s_last;
    const int j = blockIdx.x;
    const int i = threadIdx.x;

    s_xn[i] = sqrtf(g_xn2[i]);
    if (i == 0) { s_gt = 0; s_eqb = 0; s_last = 0; }
    __syncthreads();

    const float ynj = sqrtf(g_yn2[j]);
    const float v = g_dots[i * BB + j] / fmaxf(s_xn[i] * ynj, 1e-8f);
    if (i == j) s_vd = v;
    __syncthreads();
    const float vd = s_vd;

    const bool gt  = (i != j) && (v > vd);
    const bool eqb = (i != j) && (v == vd) && (i < j);
    const unsigned mgt  = __ballot_sync(0xffffffffu, gt);
    const unsigned meqb = __ballot_sync(0xffffffffu, eqb);
    if ((i & 31) == 0) {
        if (mgt)  atomicAdd(&s_gt,  __popc(mgt));
        if (meqb) atomicAdd(&s_eqb, __popc(meqb));
    }
    __syncthreads();

    if (i == 0) {
        const int rank = s_gt + s_eqb;
        atomicAdd(&g_it1,  (rank == 0) ? 1 : 0);
        atomicAdd(&g_it10, (rank < 10) ? 1 : 0);
        __threadfence();
        s_last = (atomicAdd(&g_tick, 1) == BB - 1) ? 1 : 0;
    }
    __syncthreads();

    if (s_last) {
        if (i == 0) {
            __threadfence();
            out[0] = (float)g_it1  / (float)BB;
            out[1] = (float)g_it10 / (float)BB;
            g_it1 = 0; g_it10 = 0; g_tick = 0;
        }
        __syncthreads();
        // restore zero-state (all CTAs ticked -> all reads of g_dots/norms done)
        for (int q = i; q < BB * BB; q += BB) g_dots[q] = 0.f;
        g_xn2[i] = 0.f;
        g_yn2[i] = 0.f;
    }
}

extern "C" void kernel_launch(void* const* d_in, const int* in_sizes, int n_in,
                              void* d_out, int out_size) {
    const float* Z = (const float*)d_in[0];
    const float* Y = (const float*)d_in[1];
    float* out = (float*)d_out;

    cudaFuncSetAttribute(gemm_tc_kernel, cudaFuncAttributeMaxDynamicSharedMemorySize, SMEM_TOTAL);
    gemm_tc_kernel<<<NCTA, THREADS, SMEM_TOTAL>>>(Z, Y);
    finalize_kernel<<<BB, BB>>>(out);
}